// round 11
// baseline (speedup 1.0000x reference)
#include <cuda_runtime.h>
#include <cuda_fp16.h>
#include <stdint.h>

// Problem constants
#define NB    16384
#define NL    4
#define NIS   1024
#define NHS   512
#define NOUT  3
#define NM    (NB*NL)        // 65536 rows
#define MTILE 64             // compacted rows per CTA
#define NTILE 256            // N cols per CTA (NHS split in 2)
#define KCH   64
#define NCH   (NIS/KCH)      // 16
#define NTHR  256            // 8 warps: 2 (m) x 4 (n); warp tile 32 x 64
#define CBLK  256
#define NBLK  (NM/CBLK)      // 256
#define PREPW 512            // vectorized W1 prep blocks (x4)
#define NTILES (NM/MTILE)    // 1024 max tiles

// Pre-swizzled fp16 W1 tiles: [chunk][n-half][64 k x 256 n]
__device__ __align__(16) __half g_W[NCH][2][KCH * NTILE];
// Per-half partial outputs (written only for valid rows)
__device__ float g_part[2][NM][NOUT];
// Compaction state
__device__ int   g_code[NM];
__device__ int   g_rowidx[NM];
__device__ int   g_blkcnt[NBLK];
__device__ int   g_nvalid;
__device__ float g_cstar[NOUT];     // tanh(b1) @ W2 + b2 (invalid-row output)
__device__ int   g_tilecnt[NTILES]; // per-tile arrival counters (zeroed each call)

// SMEM map (main kernel)
#define OFF_B0    0          // 32 KB (B buf 0)
#define OFF_B1    32768      // 32 KB (B buf 1)
#define OFF_A     65536      // 2 x 8 KB (A fp16 double buffer)
#define OFF_REP   81920      // 12 KB (repeat rows 1..3, fp32)
#define OFF_RED   0          // epilogue red aliases B0
#define SMEM_BYTES 94208

#define A_BUF(buf) (OFF_A + (buf) * 8192)

// ---------------- helpers ----------------
static __device__ __forceinline__ uint32_t smem_u32(const void* p) {
    uint32_t a;
    asm("{ .reg .u64 t; cvta.to.shared.u64 t, %1; cvt.u32.u64 %0, t; }"
        : "=r"(a) : "l"(p));
    return a;
}

#define CP_ASYNC16(dst, src)                                                  \
    asm volatile("cp.async.cg.shared.global [%0], [%1], 16;"                  \
                 :: "r"(dst), "l"(src))
#define CP_COMMIT() asm volatile("cp.async.commit_group;" ::: "memory")
#define CP_WAIT0()  asm volatile("cp.async.wait_group 0;" ::: "memory")

#define LDSM_X4(r, addr)                                                      \
    asm volatile("ldmatrix.sync.aligned.m8n8.x4.shared.b16 "                  \
                 "{%0,%1,%2,%3}, [%4];"                                       \
                 : "=r"((r)[0]), "=r"((r)[1]), "=r"((r)[2]), "=r"((r)[3])     \
                 : "r"(addr))

#define LDSM_X4_T(r, addr)                                                    \
    asm volatile("ldmatrix.sync.aligned.m8n8.x4.trans.shared.b16 "            \
                 "{%0,%1,%2,%3}, [%4];"                                       \
                 : "=r"((r)[0]), "=r"((r)[1]), "=r"((r)[2]), "=r"((r)[3])     \
                 : "r"(addr))

static __device__ __forceinline__ void mma16816(float* c, const uint32_t* a,
                                                const uint32_t* b) {
    asm volatile(
        "mma.sync.aligned.m16n8k16.row.col.f32.f16.f16.f32 "
        "{%0,%1,%2,%3}, {%4,%5,%6,%7}, {%8,%9}, {%0,%1,%2,%3};"
        : "+f"(c[0]), "+f"(c[1]), "+f"(c[2]), "+f"(c[3])
        : "r"(a[0]), "r"(a[1]), "r"(a[2]), "r"(a[3]), "r"(b[0]), "r"(b[1]));
}

static __device__ __forceinline__ float fast_tanh(float x) {
    float r;
    asm("tanh.approx.f32 %0, %1;" : "=f"(r) : "f"(x));
    return r;
}

static __device__ __forceinline__ int warp_incl_scan(int v, int lane) {
    #pragma unroll
    for (int o = 1; o < 32; o <<= 1) {
        int n = __shfl_up_sync(0xffffffffu, v, o);
        if (lane >= o) v += n;
    }
    return v;
}

// ---------------- K1: W1 prep (x4 vectorized) + codes/counts + c* ----------------
__global__ void prep_all(const float* __restrict__ W1,
                         const int*   __restrict__ wn,
                         const int*   __restrict__ wc,
                         const float* __restrict__ b1,
                         const float* __restrict__ W2,
                         const float* __restrict__ b2)
{
    const int b = blockIdx.x;
    const int t = threadIdx.x;

    if (b < PREPW) {
        int e4 = b * 256 + t;
        int k_g = e4 >> 7;
        int n4  = (e4 & 127) * 4;
        float4 w = *(const float4*)(W1 + (size_t)k_g * NHS + n4);
        __half2 h01 = __floats2half2_rn(w.x, w.y);
        __half2 h23 = __floats2half2_rn(w.z, w.w);
        int ch = k_g >> 6, k = k_g & 63;
        int nh = n4 >> 8, n = n4 & 255;
        int idx = k * 256 + ((((n >> 3) ^ (k & 7)) << 3) | (n & 7));
        uint2 pk;
        pk.x = *(uint32_t*)&h01;
        pk.y = *(uint32_t*)&h23;
        *(uint2*)&g_W[ch][nh][idx] = pk;
        return;
    }

    if (b < PREPW + NBLK) {
        int cb = b - PREPW;
        int m = cb * CBLK + t;
        int bb = m >> 2, l = m & 3;
        int code;
        if (l >= wn[bb]) {
            code = -2;
        } else {
            int wcl = wc[bb * 4 + l];
            int r = 0;
            for (int j = 0; j < l; j++) r += (wc[bb * 4 + j] == wcl);
            code = (r > 0) ? r : -1;
        }
        g_code[m] = code;
        int lane = t & 31, w8 = t >> 5;
        unsigned mask = __ballot_sync(0xffffffffu, code != -2);
        __shared__ int wtot[8];
        if (lane == 0) wtot[w8] = __popc(mask);
        __syncthreads();
        if (t == 0) {
            int s = 0;
            #pragma unroll
            for (int i = 0; i < 8; i++) s += wtot[i];
            g_blkcnt[cb] = s;
        }
        return;
    }

    // last block: c* = tanh(b1) @ W2 + b2 (exact fp32)
    __shared__ float r0[256], r1[256], r2[256];
    float s0 = 0.f, s1 = 0.f, s2 = 0.f;
    for (int c = t; c < NHS; c += 256) {
        float h = tanhf(b1[c]);
        s0 = fmaf(h, W2[c * 3 + 0], s0);
        s1 = fmaf(h, W2[c * 3 + 1], s1);
        s2 = fmaf(h, W2[c * 3 + 2], s2);
    }
    r0[t] = s0; r1[t] = s1; r2[t] = s2;
    __syncthreads();
    #pragma unroll
    for (int s = 128; s > 0; s >>= 1) {
        if (t < s) { r0[t] += r0[t + s]; r1[t] += r1[t + s]; r2[t] += r2[t + s]; }
        __syncthreads();
    }
    if (t == 0) {
        g_cstar[0] = r0[0] + b2[0];
        g_cstar[1] = r1[0] + b2[1];
        g_cstar[2] = r2[0] + b2[2];
    }
}

// ---------------- K2: scatter + invalid-row c* writes + tile-counter reset ----------------
__global__ void compact_scatter(float* __restrict__ out) {
    const int t = threadIdx.x;
    const int lane = t & 31, w8 = t >> 5;

    // reset per-tile counters (block 0)
    if (blockIdx.x == 0) {
        #pragma unroll
        for (int i = 0; i < NTILES / CBLK; i++) g_tilecnt[t + i * CBLK] = 0;
    }

    __shared__ int offs[NBLK];
    __shared__ int wsum[8];

    int v = g_blkcnt[t];
    int incl = warp_incl_scan(v, lane);
    if (lane == 31) wsum[w8] = incl;
    __syncthreads();
    if (t == 0) {
        int run = 0;
        #pragma unroll
        for (int i = 0; i < 8; i++) { int tmp = wsum[i]; wsum[i] = run; run += tmp; }
        if (blockIdx.x == 0) g_nvalid = run;
    }
    __syncthreads();
    offs[t] = incl - v + wsum[w8];   // exclusive
    __syncthreads();

    const int myoff = offs[blockIdx.x];

    int m = blockIdx.x * CBLK + t;
    int flag = (g_code[m] != -2);
    unsigned mask = __ballot_sync(0xffffffffu, flag);
    int pre = __popc(mask & ((1u << lane) - 1u));
    __shared__ int wtot[8], wbase[8];
    if (lane == 0) wtot[w8] = __popc(mask);
    __syncthreads();
    if (t == 0) {
        int run = 0;
        #pragma unroll
        for (int i = 0; i < 8; i++) { wbase[i] = run; run += wtot[i]; }
    }
    __syncthreads();
    if (flag) {
        g_rowidx[myoff + wbase[w8] + pre] = m;
    } else {
        out[(size_t)m * 3 + 0] = g_cstar[0];
        out[(size_t)m * 3 + 1] = g_cstar[1];
        out[(size_t)m * 3 + 2] = g_cstar[2];
    }
}

// ---------------- main fused kernel (compacted rows; fused combine) ----------------
__global__ void __launch_bounds__(NTHR, 2)
wop_main_kernel(const float* __restrict__ wenc,
                const float* __restrict__ repeat_t,
                const float* __restrict__ b1,
                const float* __restrict__ W2,
                const float* __restrict__ b2,
                float* __restrict__ out)
{
    const int bx   = blockIdx.x;
    const int tile = bx >> 1;
    const int nh   = bx & 1;
    const int nv   = g_nvalid;
    if (tile * MTILE >= nv) return;

    extern __shared__ char smem[];
    float* rep_s = (float*)(smem + OFF_REP);

    const int tid  = threadIdx.x;
    const int lane = tid & 31;
    const int wid  = tid >> 5;
    const int wm   = wid & 1;
    const int wq   = wid >> 1;

    const uint32_t sb = smem_u32(smem);

    const int arow = tid >> 2;
    const int acol = (tid & 3) * 16;
    const int kg0  = (tid & 3) * 2;

    const int slot = tile * MTILE + arow;
    int mycode = -2;
    const float* wrow = wenc;
    if (slot < nv) {
        int grow = g_rowidx[slot];
        mycode = g_code[grow];
        wrow = wenc + (size_t)grow * NIS;
    }

    #pragma unroll
    for (int i = 0; i < 12; i++) rep_s[tid + i * NTHR] = repeat_t[NIS + tid + i * NTHR];

    float4 raw[4];
    if (mycode != -2) {
        const float* p = wrow + acol;
        raw[0] = *(const float4*)(p + 0);
        raw[1] = *(const float4*)(p + 4);
        raw[2] = *(const float4*)(p + 8);
        raw[3] = *(const float4*)(p + 12);
    }
    {
        const char* s0 = (const char*)&g_W[0][nh][0];
        #pragma unroll
        for (int i = 0; i < 8; i++)
            CP_ASYNC16(sb + OFF_B0 + (tid + i * NTHR) * 16, s0 + (tid + i * NTHR) * 16);
        CP_COMMIT();
    }
    __syncthreads();

    {
        float v[16];
        #pragma unroll
        for (int i = 0; i < 4; i++) {
            v[4*i+0] = raw[i].x; v[4*i+1] = raw[i].y;
            v[4*i+2] = raw[i].z; v[4*i+3] = raw[i].w;
        }
        if (mycode == -2) {
            #pragma unroll
            for (int j = 0; j < 16; j++) v[j] = 0.f;
        } else if (mycode >= 1) {
            const float* rp = rep_s + (mycode - 1) * NIS + acol;
            #pragma unroll
            for (int j = 0; j < 16; j++) v[j] += rp[j];
        }
        #pragma unroll
        for (int c = 0; c < 2; c++) {
            uint32_t hv[4];
            #pragma unroll
            for (int p = 0; p < 4; p++) {
                __half2 hh = __floats2half2_rn(v[c*8 + 2*p], v[c*8 + 2*p + 1]);
                hv[p] = *(uint32_t*)&hh;
            }
            uint32_t soff = (uint32_t)arow * 128u + (uint32_t)(((kg0 + c) ^ (arow & 7)) << 4);
            *(uint4*)(smem + A_BUF(0) + soff) = make_uint4(hv[0], hv[1], hv[2], hv[3]);
        }
    }
    if (mycode != -2) {
        const float* p = wrow + KCH + acol;
        raw[0] = *(const float4*)(p + 0);
        raw[1] = *(const float4*)(p + 4);
        raw[2] = *(const float4*)(p + 8);
        raw[3] = *(const float4*)(p + 12);
    }

    uint32_t a_mbase[2], a_msw[2];
    {
        int mrow0 = wm * 32 + ((lane >> 3) & 1) * 8 + (lane & 7);
        a_mbase[0] = (uint32_t)mrow0 * 128u;
        a_mbase[1] = (uint32_t)(mrow0 + 16) * 128u;
        a_msw[0] = (uint32_t)(mrow0 & 7);
        a_msw[1] = (uint32_t)((mrow0 + 16) & 7);
    }
    const uint32_t a_hi_lane = (uint32_t)(lane >> 4);
    const int klocal = ((lane >> 3) & 1) * 8 + (lane & 7);
    const uint32_t b_kbase = (uint32_t)klocal * 512u;
    const uint32_t b_ksw   = (uint32_t)(klocal & 7);
    const uint32_t b_nidx0 = (uint32_t)(wq * 8 + (lane >> 4));

    float acc[2][8][4];
    #pragma unroll
    for (int i = 0; i < 2; i++)
        #pragma unroll
        for (int j = 0; j < 8; j++)
            #pragma unroll
            for (int q = 0; q < 4; q++) acc[i][j][q] = 0.f;

    #pragma unroll 1
    for (int ch = 0; ch < NCH; ch++) {
        CP_WAIT0();
        __syncthreads();

        const uint32_t bbuf  = sb + ((ch & 1) ? OFF_B1 : OFF_B0);
        const uint32_t a_buf = sb + A_BUF(ch & 1);

        if (ch < NCH - 1) {
            const char* sB = (const char*)&g_W[ch + 1][nh][0];
            uint32_t dst = sb + (((ch + 1) & 1) ? OFF_B1 : OFF_B0);
            #pragma unroll
            for (int i = 0; i < 8; i++)
                CP_ASYNC16(dst + (tid + i * NTHR) * 16, sB + (tid + i * NTHR) * 16);
            CP_COMMIT();

            float v[16];
            #pragma unroll
            for (int i = 0; i < 4; i++) {
                v[4*i+0] = raw[i].x; v[4*i+1] = raw[i].y;
                v[4*i+2] = raw[i].z; v[4*i+3] = raw[i].w;
            }
            if (mycode == -2) {
                #pragma unroll
                for (int j = 0; j < 16; j++) v[j] = 0.f;
            } else if (mycode >= 1) {
                const float* rp = rep_s + (mycode - 1) * NIS + (ch + 1) * KCH + acol;
                #pragma unroll
                for (int j = 0; j < 16; j++) v[j] += rp[j];
            }
            uint32_t abuf_w = (uint32_t)((ch + 1) & 1);
            #pragma unroll
            for (int c = 0; c < 2; c++) {
                uint32_t hv[4];
                #pragma unroll
                for (int p = 0; p < 4; p++) {
                    __half2 hh = __floats2half2_rn(v[c*8 + 2*p], v[c*8 + 2*p + 1]);
                    hv[p] = *(uint32_t*)&hh;
                }
                uint32_t soff = (uint32_t)arow * 128u + (uint32_t)(((kg0 + c) ^ (arow & 7)) << 4);
                *(uint4*)(smem + A_BUF(abuf_w) + soff) = make_uint4(hv[0], hv[1], hv[2], hv[3]);
            }
            if (ch + 2 < NCH && mycode != -2) {
                const float* p = wrow + (ch + 2) * KCH + acol;
                raw[0] = *(const float4*)(p + 0);
                raw[1] = *(const float4*)(p + 4);
                raw[2] = *(const float4*)(p + 8);
                raw[3] = *(const float4*)(p + 12);
            }
        }

        #pragma unroll
        for (int s = 0; s < 4; s++) {
            uint32_t ah[2][4], bh[4][4];
            #pragma unroll
            for (int mt = 0; mt < 2; mt++) {
                uint32_t ci  = (uint32_t)(2 * s) + a_hi_lane;
                uint32_t off = a_mbase[mt] + ((ci ^ a_msw[mt]) << 4);
                LDSM_X4(ah[mt], a_buf + off);
            }
            #pragma unroll
            for (int np = 0; np < 4; np++) {
                uint32_t offB = (uint32_t)(s * 8192) + b_kbase +
                                (((b_nidx0 + (uint32_t)(2 * np)) ^ b_ksw) << 4);
                LDSM_X4_T(bh[np], bbuf + offB);
            }
            #pragma unroll
            for (int np = 0; np < 4; np++) {
                #pragma unroll
                for (int mt = 0; mt < 2; mt++) {
                    #pragma unroll
                    for (int nn = 0; nn < 2; nn++) {
                        mma16816(acc[mt][np * 2 + nn], ah[mt], bh[np] + 2 * nn);
                    }
                }
            }
        }
    }

    // ---- epilogue: +b1, tanh, partial x W2, write g_part ----
    __syncthreads();
    float* red = (float*)(smem + OFF_RED);
    const int rslot = wq * 4 + (lane & 3);
    #pragma unroll
    for (int mt = 0; mt < 2; mt++) {
        #pragma unroll
        for (int rh = 0; rh < 2; rh++) {
            float s0 = 0.f, s1 = 0.f, s2 = 0.f;
            #pragma unroll
            for (int nt = 0; nt < 8; nt++) {
                int col_g = nh * NTILE + wq * 64 + nt * 8 + (lane & 3) * 2;
                #pragma unroll
                for (int cc = 0; cc < 2; cc++) {
                    float h = fast_tanh(acc[mt][nt][rh * 2 + cc] + b1[col_g + cc]);
                    s0 = fmaf(h, W2[(col_g + cc) * 3 + 0], s0);
                    s1 = fmaf(h, W2[(col_g + cc) * 3 + 1], s1);
                    s2 = fmaf(h, W2[(col_g + cc) * 3 + 2], s2);
                }
            }
            int row = wm * 32 + mt * 16 + rh * 8 + (lane >> 2);
            float* rp = red + (size_t)row * 48 + rslot * 3;
            rp[0] = s0; rp[1] = s1; rp[2] = s2;
        }
    }
    __syncthreads();
    if (tid < MTILE) {
        int oslot = tile * MTILE + tid;
        if (oslot < nv) {
            float s0 = 0.f, s1 = 0.f, s2 = 0.f;
            const float* rp = red + (size_t)tid * 48;
            #pragma unroll
            for (int s = 0; s < 16; s++) {
                s0 += rp[s * 3 + 0];
                s1 += rp[s * 3 + 1];
                s2 += rp[s * 3 + 2];
            }
            int grow = g_rowidx[oslot];
            g_part[nh][grow][0] = s0;
            g_part[nh][grow][1] = s1;
            g_part[nh][grow][2] = s2;
        }
    }

    // ---- fused combine: second-arriving CTA of the tile sums both halves ----
    __threadfence();          // make this CTA's g_part writes globally visible
    __syncthreads();
    __shared__ int amLast;
    if (tid == 0) amLast = (atomicAdd(&g_tilecnt[tile], 1) == 1);
    __syncthreads();
    if (amLast && tid < MTILE) {
        int oslot = tile * MTILE + tid;
        if (oslot < nv) {
            int grow = g_rowidx[oslot];
            // fixed evaluation order -> bit-identical regardless of which CTA combines
            out[(size_t)grow * 3 + 0] = g_part[0][grow][0] + g_part[1][grow][0] + b2[0];
            out[(size_t)grow * 3 + 1] = g_part[0][grow][1] + g_part[1][grow][1] + b2[1];
            out[(size_t)grow * 3 + 2] = g_part[0][grow][2] + g_part[1][grow][2] + b2[2];
        }
    }
}

// ---------------- launch ----------------
extern "C" void kernel_launch(void* const* d_in, const int* in_sizes, int n_in,
                              void* d_out, int out_size) {
    const float* wenc   = (const float*)d_in[0];
    const float* repeat = (const float*)d_in[1];
    const float* W1     = (const float*)d_in[2];
    const float* b1     = (const float*)d_in[3];
    const float* W2     = (const float*)d_in[4];
    const float* b2     = (const float*)d_in[5];
    const int*   wn     = (const int*)d_in[6];
    const int*   wc     = (const int*)d_in[7];
    float* out = (float*)d_out;
    (void)in_sizes; (void)n_in; (void)out_size;

    prep_all<<<PREPW + NBLK + 1, 256>>>(W1, wn, wc, b1, W2, b2);
    compact_scatter<<<NBLK, CBLK>>>(out);

    cudaFuncSetAttribute(wop_main_kernel,
                         cudaFuncAttributeMaxDynamicSharedMemorySize, SMEM_BYTES);
    wop_main_kernel<<<NTILES * 2, NTHR, SMEM_BYTES>>>(
        wenc, repeat, b1, W2, b2, out);
}

// round 12
// speedup vs baseline: 1.1742x; 1.1742x over previous
#include <cuda_runtime.h>
#include <cuda_fp16.h>
#include <stdint.h>

// Problem constants
#define NB    16384
#define NL    4
#define NIS   1024
#define NHS   512
#define NOUT  3
#define NM    (NB*NL)        // 65536 rows
#define MTILE 64             // compacted rows per CTA
#define NTILE 256            // N cols per CTA (NHS split in 2)
#define KCH   64
#define NCH   (NIS/KCH)      // 16
#define NTHR  256            // 8 warps: 2 (m) x 4 (n); warp tile 32 x 64
#define CBLK  256
#define NBLK  (NM/CBLK)      // 256
#define PREPW 512            // vectorized W1 prep blocks (x4)

// Pre-swizzled fp16 W1 tiles: [chunk][n-half][64 k x 256 n]
__device__ __align__(16) __half g_W[NCH][2][KCH * NTILE];
// Per-half partial outputs (written only for valid rows)
__device__ float g_part[2][NM][NOUT];
// Compaction state
__device__ int   g_code[NM];
__device__ int   g_rowidx[NM];
__device__ int   g_blkcnt[NBLK];
__device__ int   g_nvalid;
__device__ float g_cstar[NOUT];   // tanh(b1) @ W2 + b2 (invalid-row output)

// SMEM map (main kernel)
#define OFF_B0    0          // 32 KB (B buf 0)
#define OFF_B1    32768      // 32 KB (B buf 1)
#define OFF_A     65536      // 2 x 8 KB (A fp16 double buffer)
#define OFF_REP   81920      // 12 KB (repeat rows 1..3, fp32)
#define OFF_RED   0          // epilogue red aliases B0
#define SMEM_BYTES 94208

#define A_BUF(buf) (OFF_A + (buf) * 8192)

// ---------------- helpers ----------------
static __device__ __forceinline__ uint32_t smem_u32(const void* p) {
    uint32_t a;
    asm("{ .reg .u64 t; cvta.to.shared.u64 t, %1; cvt.u32.u64 %0, t; }"
        : "=r"(a) : "l"(p));
    return a;
}

#define CP_ASYNC16(dst, src)                                                  \
    asm volatile("cp.async.cg.shared.global [%0], [%1], 16;"                  \
                 :: "r"(dst), "l"(src))
#define CP_COMMIT() asm volatile("cp.async.commit_group;" ::: "memory")
#define CP_WAIT0()  asm volatile("cp.async.wait_group 0;" ::: "memory")

#define LDSM_X4(r, addr)                                                      \
    asm volatile("ldmatrix.sync.aligned.m8n8.x4.shared.b16 "                  \
                 "{%0,%1,%2,%3}, [%4];"                                       \
                 : "=r"((r)[0]), "=r"((r)[1]), "=r"((r)[2]), "=r"((r)[3])     \
                 : "r"(addr))

#define LDSM_X4_T(r, addr)                                                    \
    asm volatile("ldmatrix.sync.aligned.m8n8.x4.trans.shared.b16 "            \
                 "{%0,%1,%2,%3}, [%4];"                                       \
                 : "=r"((r)[0]), "=r"((r)[1]), "=r"((r)[2]), "=r"((r)[3])     \
                 : "r"(addr))

static __device__ __forceinline__ void mma16816(float* c, const uint32_t* a,
                                                const uint32_t* b) {
    asm volatile(
        "mma.sync.aligned.m16n8k16.row.col.f32.f16.f16.f32 "
        "{%0,%1,%2,%3}, {%4,%5,%6,%7}, {%8,%9}, {%0,%1,%2,%3};"
        : "+f"(c[0]), "+f"(c[1]), "+f"(c[2]), "+f"(c[3])
        : "r"(a[0]), "r"(a[1]), "r"(a[2]), "r"(a[3]), "r"(b[0]), "r"(b[1]));
}

static __device__ __forceinline__ float fast_tanh(float x) {
    float r;
    asm("tanh.approx.f32 %0, %1;" : "=f"(r) : "f"(x));
    return r;
}

static __device__ __forceinline__ int warp_incl_scan(int v, int lane) {
    #pragma unroll
    for (int o = 1; o < 32; o <<= 1) {
        int n = __shfl_up_sync(0xffffffffu, v, o);
        if (lane >= o) v += n;
    }
    return v;
}

// ---------------- K1: W1 prep (x4 vectorized) + codes/counts + c* ----------------
__global__ void prep_all(const float* __restrict__ W1,
                         const int*   __restrict__ wn,
                         const int*   __restrict__ wc,
                         const float* __restrict__ b1,
                         const float* __restrict__ W2,
                         const float* __restrict__ b2)
{
    const int b = blockIdx.x;
    const int t = threadIdx.x;

    if (b < PREPW) {
        int e4 = b * 256 + t;
        int k_g = e4 >> 7;
        int n4  = (e4 & 127) * 4;
        float4 w = *(const float4*)(W1 + (size_t)k_g * NHS + n4);
        __half2 h01 = __floats2half2_rn(w.x, w.y);
        __half2 h23 = __floats2half2_rn(w.z, w.w);
        int ch = k_g >> 6, k = k_g & 63;
        int nh = n4 >> 8, n = n4 & 255;
        int idx = k * 256 + ((((n >> 3) ^ (k & 7)) << 3) | (n & 7));
        uint2 pk;
        pk.x = *(uint32_t*)&h01;
        pk.y = *(uint32_t*)&h23;
        *(uint2*)&g_W[ch][nh][idx] = pk;
        return;
    }

    if (b < PREPW + NBLK) {
        int cb = b - PREPW;
        int m = cb * CBLK + t;
        int bb = m >> 2, l = m & 3;
        int code;
        if (l >= wn[bb]) {
            code = -2;
        } else {
            int wcl = wc[bb * 4 + l];
            int r = 0;
            for (int j = 0; j < l; j++) r += (wc[bb * 4 + j] == wcl);
            code = (r > 0) ? r : -1;
        }
        g_code[m] = code;
        int lane = t & 31, w8 = t >> 5;
        unsigned mask = __ballot_sync(0xffffffffu, code != -2);
        __shared__ int wtot[8];
        if (lane == 0) wtot[w8] = __popc(mask);
        __syncthreads();
        if (t == 0) {
            int s = 0;
            #pragma unroll
            for (int i = 0; i < 8; i++) s += wtot[i];
            g_blkcnt[cb] = s;
        }
        return;
    }

    // last block: c* = tanh(b1) @ W2 + b2 (exact fp32)
    __shared__ float r0[256], r1[256], r2[256];
    float s0 = 0.f, s1 = 0.f, s2 = 0.f;
    for (int c = t; c < NHS; c += 256) {
        float h = tanhf(b1[c]);
        s0 = fmaf(h, W2[c * 3 + 0], s0);
        s1 = fmaf(h, W2[c * 3 + 1], s1);
        s2 = fmaf(h, W2[c * 3 + 2], s2);
    }
    r0[t] = s0; r1[t] = s1; r2[t] = s2;
    __syncthreads();
    #pragma unroll
    for (int s = 128; s > 0; s >>= 1) {
        if (t < s) { r0[t] += r0[t + s]; r1[t] += r1[t + s]; r2[t] += r2[t + s]; }
        __syncthreads();
    }
    if (t == 0) {
        g_cstar[0] = r0[0] + b2[0];
        g_cstar[1] = r1[0] + b2[1];
        g_cstar[2] = r2[0] + b2[2];
    }
}

// ---------------- K2: scatter + invalid-row c* writes ----------------
__global__ void compact_scatter(float* __restrict__ out) {
    const int t = threadIdx.x;
    const int lane = t & 31, w8 = t >> 5;

    __shared__ int offs[NBLK];
    __shared__ int wsum[8];

    int v = g_blkcnt[t];
    int incl = warp_incl_scan(v, lane);
    if (lane == 31) wsum[w8] = incl;
    __syncthreads();
    if (t == 0) {
        int run = 0;
        #pragma unroll
        for (int i = 0; i < 8; i++) { int tmp = wsum[i]; wsum[i] = run; run += tmp; }
        if (blockIdx.x == 0) g_nvalid = run;
    }
    __syncthreads();
    offs[t] = incl - v + wsum[w8];   // exclusive
    __syncthreads();

    const int myoff = offs[blockIdx.x];

    int m = blockIdx.x * CBLK + t;
    int flag = (g_code[m] != -2);
    unsigned mask = __ballot_sync(0xffffffffu, flag);
    int pre = __popc(mask & ((1u << lane) - 1u));
    __shared__ int wtot[8], wbase[8];
    if (lane == 0) wtot[w8] = __popc(mask);
    __syncthreads();
    if (t == 0) {
        int run = 0;
        #pragma unroll
        for (int i = 0; i < 8; i++) { wbase[i] = run; run += wtot[i]; }
    }
    __syncthreads();
    if (flag) {
        g_rowidx[myoff + wbase[w8] + pre] = m;
    } else {
        out[(size_t)m * 3 + 0] = g_cstar[0];
        out[(size_t)m * 3 + 1] = g_cstar[1];
        out[(size_t)m * 3 + 2] = g_cstar[2];
    }
}

// ---------------- main fused kernel (compacted rows) ----------------
__global__ void __launch_bounds__(NTHR, 2)
wop_main_kernel(const float* __restrict__ wenc,
                const float* __restrict__ repeat_t,
                const float* __restrict__ b1,
                const float* __restrict__ W2)
{
    const int bx   = blockIdx.x;
    const int tile = bx >> 1;
    const int nh   = bx & 1;
    const int nv   = g_nvalid;
    if (tile * MTILE >= nv) return;

    extern __shared__ char smem[];
    float* rep_s = (float*)(smem + OFF_REP);

    const int tid  = threadIdx.x;
    const int lane = tid & 31;
    const int wid  = tid >> 5;
    const int wm   = wid & 1;
    const int wq   = wid >> 1;

    const uint32_t sb = smem_u32(smem);

    const int arow = tid >> 2;
    const int acol = (tid & 3) * 16;
    const int kg0  = (tid & 3) * 2;

    const int slot = tile * MTILE + arow;
    int mycode = -2;
    const float* wrow = wenc;
    if (slot < nv) {
        int grow = g_rowidx[slot];
        mycode = g_code[grow];
        wrow = wenc + (size_t)grow * NIS;
    }

    #pragma unroll
    for (int i = 0; i < 12; i++) rep_s[tid + i * NTHR] = repeat_t[NIS + tid + i * NTHR];

    float4 raw[4];
    if (mycode != -2) {
        const float* p = wrow + acol;
        raw[0] = *(const float4*)(p + 0);
        raw[1] = *(const float4*)(p + 4);
        raw[2] = *(const float4*)(p + 8);
        raw[3] = *(const float4*)(p + 12);
    }
    {
        const char* s0 = (const char*)&g_W[0][nh][0];
        #pragma unroll
        for (int i = 0; i < 8; i++)
            CP_ASYNC16(sb + OFF_B0 + (tid + i * NTHR) * 16, s0 + (tid + i * NTHR) * 16);
        CP_COMMIT();
    }
    __syncthreads();

    {
        float v[16];
        #pragma unroll
        for (int i = 0; i < 4; i++) {
            v[4*i+0] = raw[i].x; v[4*i+1] = raw[i].y;
            v[4*i+2] = raw[i].z; v[4*i+3] = raw[i].w;
        }
        if (mycode == -2) {
            #pragma unroll
            for (int j = 0; j < 16; j++) v[j] = 0.f;
        } else if (mycode >= 1) {
            const float* rp = rep_s + (mycode - 1) * NIS + acol;
            #pragma unroll
            for (int j = 0; j < 16; j++) v[j] += rp[j];
        }
        #pragma unroll
        for (int c = 0; c < 2; c++) {
            uint32_t hv[4];
            #pragma unroll
            for (int p = 0; p < 4; p++) {
                __half2 hh = __floats2half2_rn(v[c*8 + 2*p], v[c*8 + 2*p + 1]);
                hv[p] = *(uint32_t*)&hh;
            }
            uint32_t soff = (uint32_t)arow * 128u + (uint32_t)(((kg0 + c) ^ (arow & 7)) << 4);
            *(uint4*)(smem + A_BUF(0) + soff) = make_uint4(hv[0], hv[1], hv[2], hv[3]);
        }
    }
    if (mycode != -2) {
        const float* p = wrow + KCH + acol;
        raw[0] = *(const float4*)(p + 0);
        raw[1] = *(const float4*)(p + 4);
        raw[2] = *(const float4*)(p + 8);
        raw[3] = *(const float4*)(p + 12);
    }

    uint32_t a_mbase[2], a_msw[2];
    {
        int mrow0 = wm * 32 + ((lane >> 3) & 1) * 8 + (lane & 7);
        a_mbase[0] = (uint32_t)mrow0 * 128u;
        a_mbase[1] = (uint32_t)(mrow0 + 16) * 128u;
        a_msw[0] = (uint32_t)(mrow0 & 7);
        a_msw[1] = (uint32_t)((mrow0 + 16) & 7);
    }
    const uint32_t a_hi_lane = (uint32_t)(lane >> 4);
    const int klocal = ((lane >> 3) & 1) * 8 + (lane & 7);
    const uint32_t b_kbase = (uint32_t)klocal * 512u;
    const uint32_t b_ksw   = (uint32_t)(klocal & 7);
    const uint32_t b_nidx0 = (uint32_t)(wq * 8 + (lane >> 4));

    float acc[2][8][4];
    #pragma unroll
    for (int i = 0; i < 2; i++)
        #pragma unroll
        for (int j = 0; j < 8; j++)
            #pragma unroll
            for (int q = 0; q < 4; q++) acc[i][j][q] = 0.f;

    #pragma unroll 1
    for (int ch = 0; ch < NCH; ch++) {
        CP_WAIT0();
        __syncthreads();

        const uint32_t bbuf  = sb + ((ch & 1) ? OFF_B1 : OFF_B0);
        const uint32_t a_buf = sb + A_BUF(ch & 1);

        if (ch < NCH - 1) {
            const char* sB = (const char*)&g_W[ch + 1][nh][0];
            uint32_t dst = sb + (((ch + 1) & 1) ? OFF_B1 : OFF_B0);
            #pragma unroll
            for (int i = 0; i < 8; i++)
                CP_ASYNC16(dst + (tid + i * NTHR) * 16, sB + (tid + i * NTHR) * 16);
            CP_COMMIT();

            float v[16];
            #pragma unroll
            for (int i = 0; i < 4; i++) {
                v[4*i+0] = raw[i].x; v[4*i+1] = raw[i].y;
                v[4*i+2] = raw[i].z; v[4*i+3] = raw[i].w;
            }
            if (mycode == -2) {
                #pragma unroll
                for (int j = 0; j < 16; j++) v[j] = 0.f;
            } else if (mycode >= 1) {
                const float* rp = rep_s + (mycode - 1) * NIS + (ch + 1) * KCH + acol;
                #pragma unroll
                for (int j = 0; j < 16; j++) v[j] += rp[j];
            }
            uint32_t abuf_w = (uint32_t)((ch + 1) & 1);
            #pragma unroll
            for (int c = 0; c < 2; c++) {
                uint32_t hv[4];
                #pragma unroll
                for (int p = 0; p < 4; p++) {
                    __half2 hh = __floats2half2_rn(v[c*8 + 2*p], v[c*8 + 2*p + 1]);
                    hv[p] = *(uint32_t*)&hh;
                }
                uint32_t soff = (uint32_t)arow * 128u + (uint32_t)(((kg0 + c) ^ (arow & 7)) << 4);
                *(uint4*)(smem + A_BUF(abuf_w) + soff) = make_uint4(hv[0], hv[1], hv[2], hv[3]);
            }
            if (ch + 2 < NCH && mycode != -2) {
                const float* p = wrow + (ch + 2) * KCH + acol;
                raw[0] = *(const float4*)(p + 0);
                raw[1] = *(const float4*)(p + 4);
                raw[2] = *(const float4*)(p + 8);
                raw[3] = *(const float4*)(p + 12);
            }
        }

        #pragma unroll
        for (int s = 0; s < 4; s++) {
            uint32_t ah[2][4], bh[4][4];
            #pragma unroll
            for (int mt = 0; mt < 2; mt++) {
                uint32_t ci  = (uint32_t)(2 * s) + a_hi_lane;
                uint32_t off = a_mbase[mt] + ((ci ^ a_msw[mt]) << 4);
                LDSM_X4(ah[mt], a_buf + off);
            }
            #pragma unroll
            for (int np = 0; np < 4; np++) {
                uint32_t offB = (uint32_t)(s * 8192) + b_kbase +
                                (((b_nidx0 + (uint32_t)(2 * np)) ^ b_ksw) << 4);
                LDSM_X4_T(bh[np], bbuf + offB);
            }
            #pragma unroll
            for (int np = 0; np < 4; np++) {
                #pragma unroll
                for (int mt = 0; mt < 2; mt++) {
                    #pragma unroll
                    for (int nn = 0; nn < 2; nn++) {
                        mma16816(acc[mt][np * 2 + nn], ah[mt], bh[np] + 2 * nn);
                    }
                }
            }
        }
    }

    // ---- epilogue ----
    __syncthreads();
    float* red = (float*)(smem + OFF_RED);
    const int rslot = wq * 4 + (lane & 3);
    #pragma unroll
    for (int mt = 0; mt < 2; mt++) {
        #pragma unroll
        for (int rh = 0; rh < 2; rh++) {
            float s0 = 0.f, s1 = 0.f, s2 = 0.f;
            #pragma unroll
            for (int nt = 0; nt < 8; nt++) {
                int col_g = nh * NTILE + wq * 64 + nt * 8 + (lane & 3) * 2;
                #pragma unroll
                for (int cc = 0; cc < 2; cc++) {
                    float h = fast_tanh(acc[mt][nt][rh * 2 + cc] + b1[col_g + cc]);
                    s0 = fmaf(h, W2[(col_g + cc) * 3 + 0], s0);
                    s1 = fmaf(h, W2[(col_g + cc) * 3 + 1], s1);
                    s2 = fmaf(h, W2[(col_g + cc) * 3 + 2], s2);
                }
            }
            int row = wm * 32 + mt * 16 + rh * 8 + (lane >> 2);
            float* rp = red + (size_t)row * 48 + rslot * 3;
            rp[0] = s0; rp[1] = s1; rp[2] = s2;
        }
    }
    __syncthreads();
    if (tid < MTILE) {
        int oslot = tile * MTILE + tid;
        if (oslot < nv) {
            float s0 = 0.f, s1 = 0.f, s2 = 0.f;
            const float* rp = red + (size_t)tid * 48;
            #pragma unroll
            for (int s = 0; s < 16; s++) {
                s0 += rp[s * 3 + 0];
                s1 += rp[s * 3 + 1];
                s2 += rp[s * 3 + 2];
            }
            int grow = g_rowidx[oslot];
            g_part[nh][grow][0] = s0;
            g_part[nh][grow][1] = s1;
            g_part[nh][grow][2] = s2;
        }
    }
}

// ---------------- combine: valid rows only, 1 row per thread ----------------
__global__ void combine_kernel(const float* __restrict__ b2,
                               float* __restrict__ out) {
    int m = blockIdx.x * blockDim.x + threadIdx.x;
    if (m >= NM) return;
    if (g_code[m] != -2) {
        out[(size_t)m * 3 + 0] = g_part[0][m][0] + g_part[1][m][0] + b2[0];
        out[(size_t)m * 3 + 1] = g_part[0][m][1] + g_part[1][m][1] + b2[1];
        out[(size_t)m * 3 + 2] = g_part[0][m][2] + g_part[1][m][2] + b2[2];
    }
}

// ---------------- launch ----------------
extern "C" void kernel_launch(void* const* d_in, const int* in_sizes, int n_in,
                              void* d_out, int out_size) {
    const float* wenc   = (const float*)d_in[0];
    const float* repeat = (const float*)d_in[1];
    const float* W1     = (const float*)d_in[2];
    const float* b1     = (const float*)d_in[3];
    const float* W2     = (const float*)d_in[4];
    const float* b2     = (const float*)d_in[5];
    const int*   wn     = (const int*)d_in[6];
    const int*   wc     = (const int*)d_in[7];
    float* out = (float*)d_out;
    (void)in_sizes; (void)n_in; (void)out_size;

    prep_all<<<PREPW + NBLK + 1, 256>>>(W1, wn, wc, b1, W2, b2);
    compact_scatter<<<NBLK, CBLK>>>(out);

    cudaFuncSetAttribute(wop_main_kernel,
                         cudaFuncAttributeMaxDynamicSharedMemorySize, SMEM_BYTES);
    wop_main_kernel<<<(NM / MTILE) * 2, NTHR, SMEM_BYTES>>>(
        wenc, repeat, b1, W2);

    combine_kernel<<<(NM + 255) / 256, 256>>>(b2, out);
}

// round 13
// speedup vs baseline: 1.1808x; 1.0056x over previous
#include <cuda_runtime.h>
#include <cuda_fp16.h>
#include <stdint.h>

// Problem constants
#define NB    16384
#define NL    4
#define NIS   1024
#define NHS   512
#define NOUT  3
#define NM    (NB*NL)        // 65536 rows
#define MTILE 64             // compacted rows per CTA
#define NTILE 256            // N cols per CTA (NHS split in 2)
#define KCH   64
#define NCH   (NIS/KCH)      // 16
#define NTHR  256            // 8 warps: 2 (m) x 4 (n); warp tile 32 x 64
#define CBLK  256
#define NBLK  (NM/CBLK)      // 256
#define PREPW 512            // vectorized W1 prep blocks (x4)

// Pre-swizzled fp16 W1 tiles: [chunk][n-half][64 k x 256 n]
__device__ __align__(16) __half g_W[NCH][2][KCH * NTILE];
// Per-half partial outputs (written only for valid rows)
__device__ float g_part[2][NM][NOUT];
// Compaction state
__device__ int   g_code[NM];
__device__ int   g_rowidx[NM];
__device__ int   g_blkcnt[NBLK];
__device__ int   g_nvalid;
__device__ float g_cstar[NOUT];   // tanh(b1) @ W2 + b2 (invalid-row output)

// SMEM map (main kernel)
#define OFF_B0    0          // 32 KB (B buf 0)
#define OFF_B1    32768      // 32 KB (B buf 1)
#define OFF_A     65536      // 2 x 8 KB (A fp16 double buffer)
#define OFF_REP   81920      // 12 KB (repeat rows 1..3, fp32)
#define OFF_RED   0          // epilogue red aliases B0
#define SMEM_BYTES 94208

#define A_BUF(buf) (OFF_A + (buf) * 8192)

// ---------------- helpers ----------------
static __device__ __forceinline__ uint32_t smem_u32(const void* p) {
    uint32_t a;
    asm("{ .reg .u64 t; cvta.to.shared.u64 t, %1; cvt.u32.u64 %0, t; }"
        : "=r"(a) : "l"(p));
    return a;
}

#define CP_ASYNC16(dst, src)                                                  \
    asm volatile("cp.async.cg.shared.global [%0], [%1], 16;"                  \
                 :: "r"(dst), "l"(src))
#define CP_COMMIT() asm volatile("cp.async.commit_group;" ::: "memory")
#define CP_WAIT0()  asm volatile("cp.async.wait_group 0;" ::: "memory")

#define LDSM_X4(r, addr)                                                      \
    asm volatile("ldmatrix.sync.aligned.m8n8.x4.shared.b16 "                  \
                 "{%0,%1,%2,%3}, [%4];"                                       \
                 : "=r"((r)[0]), "=r"((r)[1]), "=r"((r)[2]), "=r"((r)[3])     \
                 : "r"(addr))

#define LDSM_X4_T(r, addr)                                                    \
    asm volatile("ldmatrix.sync.aligned.m8n8.x4.trans.shared.b16 "            \
                 "{%0,%1,%2,%3}, [%4];"                                       \
                 : "=r"((r)[0]), "=r"((r)[1]), "=r"((r)[2]), "=r"((r)[3])     \
                 : "r"(addr))

static __device__ __forceinline__ void mma16816(float* c, const uint32_t* a,
                                                const uint32_t* b) {
    asm volatile(
        "mma.sync.aligned.m16n8k16.row.col.f32.f16.f16.f32 "
        "{%0,%1,%2,%3}, {%4,%5,%6,%7}, {%8,%9}, {%0,%1,%2,%3};"
        : "+f"(c[0]), "+f"(c[1]), "+f"(c[2]), "+f"(c[3])
        : "r"(a[0]), "r"(a[1]), "r"(a[2]), "r"(a[3]), "r"(b[0]), "r"(b[1]));
}

static __device__ __forceinline__ float fast_tanh(float x) {
    float r;
    asm("tanh.approx.f32 %0, %1;" : "=f"(r) : "f"(x));
    return r;
}

static __device__ __forceinline__ int warp_incl_scan(int v, int lane) {
    #pragma unroll
    for (int o = 1; o < 32; o <<= 1) {
        int n = __shfl_up_sync(0xffffffffu, v, o);
        if (lane >= o) v += n;
    }
    return v;
}

// ---------------- K1: W1 prep (x4 vectorized) + codes/counts + c* ----------------
__global__ void prep_all(const float* __restrict__ W1,
                         const int*   __restrict__ wn,
                         const int*   __restrict__ wc,
                         const float* __restrict__ b1,
                         const float* __restrict__ W2,
                         const float* __restrict__ b2)
{
    const int b = blockIdx.x;
    const int t = threadIdx.x;

    if (b < PREPW) {
        int e4 = b * 256 + t;
        int k_g = e4 >> 7;
        int n4  = (e4 & 127) * 4;
        float4 w = *(const float4*)(W1 + (size_t)k_g * NHS + n4);
        __half2 h01 = __floats2half2_rn(w.x, w.y);
        __half2 h23 = __floats2half2_rn(w.z, w.w);
        int ch = k_g >> 6, k = k_g & 63;
        int nh = n4 >> 8, n = n4 & 255;
        int idx = k * 256 + ((((n >> 3) ^ (k & 7)) << 3) | (n & 7));
        uint2 pk;
        pk.x = *(uint32_t*)&h01;
        pk.y = *(uint32_t*)&h23;
        *(uint2*)&g_W[ch][nh][idx] = pk;
        return;
    }

    if (b < PREPW + NBLK) {
        int cb = b - PREPW;
        int m = cb * CBLK + t;
        int bb = m >> 2, l = m & 3;
        int code;
        if (l >= wn[bb]) {
            code = -2;
        } else {
            int wcl = wc[bb * 4 + l];
            int r = 0;
            for (int j = 0; j < l; j++) r += (wc[bb * 4 + j] == wcl);
            code = (r > 0) ? r : -1;
        }
        g_code[m] = code;
        int lane = t & 31, w8 = t >> 5;
        unsigned mask = __ballot_sync(0xffffffffu, code != -2);
        __shared__ int wtot[8];
        if (lane == 0) wtot[w8] = __popc(mask);
        __syncthreads();
        if (t == 0) {
            int s = 0;
            #pragma unroll
            for (int i = 0; i < 8; i++) s += wtot[i];
            g_blkcnt[cb] = s;
        }
        return;
    }

    // last block: c* = tanh(b1) @ W2 + b2 (exact fp32)
    __shared__ float r0[256], r1[256], r2[256];
    float s0 = 0.f, s1 = 0.f, s2 = 0.f;
    for (int c = t; c < NHS; c += 256) {
        float h = tanhf(b1[c]);
        s0 = fmaf(h, W2[c * 3 + 0], s0);
        s1 = fmaf(h, W2[c * 3 + 1], s1);
        s2 = fmaf(h, W2[c * 3 + 2], s2);
    }
    r0[t] = s0; r1[t] = s1; r2[t] = s2;
    __syncthreads();
    #pragma unroll
    for (int s = 128; s > 0; s >>= 1) {
        if (t < s) { r0[t] += r0[t + s]; r1[t] += r1[t + s]; r2[t] += r2[t + s]; }
        __syncthreads();
    }
    if (t == 0) {
        g_cstar[0] = r0[0] + b2[0];
        g_cstar[1] = r1[0] + b2[1];
        g_cstar[2] = r2[0] + b2[2];
    }
}

// ---------------- K2: scatter + invalid-row c* writes ----------------
__global__ void compact_scatter(float* __restrict__ out) {
    const int t = threadIdx.x;
    const int lane = t & 31, w8 = t >> 5;

    __shared__ int offs[NBLK];
    __shared__ int wsum[8];

    int v = g_blkcnt[t];
    int incl = warp_incl_scan(v, lane);
    if (lane == 31) wsum[w8] = incl;
    __syncthreads();
    if (t == 0) {
        int run = 0;
        #pragma unroll
        for (int i = 0; i < 8; i++) { int tmp = wsum[i]; wsum[i] = run; run += tmp; }
        if (blockIdx.x == 0) g_nvalid = run;
    }
    __syncthreads();
    offs[t] = incl - v + wsum[w8];   // exclusive
    __syncthreads();

    const int myoff = offs[blockIdx.x];

    int m = blockIdx.x * CBLK + t;
    int flag = (g_code[m] != -2);
    unsigned mask = __ballot_sync(0xffffffffu, flag);
    int pre = __popc(mask & ((1u << lane) - 1u));
    __shared__ int wtot[8], wbase[8];
    if (lane == 0) wtot[w8] = __popc(mask);
    __syncthreads();
    if (t == 0) {
        int run = 0;
        #pragma unroll
        for (int i = 0; i < 8; i++) { wbase[i] = run; run += wtot[i]; }
    }
    __syncthreads();
    if (flag) {
        g_rowidx[myoff + wbase[w8] + pre] = m;
    } else {
        out[(size_t)m * 3 + 0] = g_cstar[0];
        out[(size_t)m * 3 + 1] = g_cstar[1];
        out[(size_t)m * 3 + 2] = g_cstar[2];
    }
}

// ---------------- main fused kernel (compacted rows) ----------------
__global__ void __launch_bounds__(NTHR, 2)
wop_main_kernel(const float* __restrict__ wenc,
                const float* __restrict__ repeat_t,
                const float* __restrict__ b1,
                const float* __restrict__ W2)
{
    const int bx   = blockIdx.x;
    const int tile = bx >> 1;
    const int nh   = bx & 1;
    const int nv   = g_nvalid;
    if (tile * MTILE >= nv) return;

    extern __shared__ char smem[];
    float* rep_s = (float*)(smem + OFF_REP);

    const int tid  = threadIdx.x;
    const int lane = tid & 31;
    const int wid  = tid >> 5;
    const int wm   = wid & 1;
    const int wq   = wid >> 1;

    const uint32_t sb = smem_u32(smem);

    const int arow = tid >> 2;
    const int acol = (tid & 3) * 16;
    const int kg0  = (tid & 3) * 2;

    const int slot = tile * MTILE + arow;
    int mycode = -2;
    const float* wrow = wenc;
    if (slot < nv) {
        int grow = g_rowidx[slot];
        mycode = g_code[grow];
        wrow = wenc + (size_t)grow * NIS;
    }

    #pragma unroll
    for (int i = 0; i < 12; i++) rep_s[tid + i * NTHR] = repeat_t[NIS + tid + i * NTHR];

    float4 raw[4];
    if (mycode != -2) {
        const float* p = wrow + acol;
        raw[0] = *(const float4*)(p + 0);
        raw[1] = *(const float4*)(p + 4);
        raw[2] = *(const float4*)(p + 8);
        raw[3] = *(const float4*)(p + 12);
    }
    {
        const char* s0 = (const char*)&g_W[0][nh][0];
        #pragma unroll
        for (int i = 0; i < 8; i++)
            CP_ASYNC16(sb + OFF_B0 + (tid + i * NTHR) * 16, s0 + (tid + i * NTHR) * 16);
        CP_COMMIT();
    }
    __syncthreads();   // rep_s visible

    // convert + store A(0)
    {
        float v[16];
        #pragma unroll
        for (int i = 0; i < 4; i++) {
            v[4*i+0] = raw[i].x; v[4*i+1] = raw[i].y;
            v[4*i+2] = raw[i].z; v[4*i+3] = raw[i].w;
        }
        if (mycode == -2) {
            #pragma unroll
            for (int j = 0; j < 16; j++) v[j] = 0.f;
        } else if (mycode >= 1) {
            const float* rp = rep_s + (mycode - 1) * NIS + acol;
            #pragma unroll
            for (int j = 0; j < 16; j++) v[j] += rp[j];
        }
        #pragma unroll
        for (int c = 0; c < 2; c++) {
            uint32_t hv[4];
            #pragma unroll
            for (int p = 0; p < 4; p++) {
                __half2 hh = __floats2half2_rn(v[c*8 + 2*p], v[c*8 + 2*p + 1]);
                hv[p] = *(uint32_t*)&hh;
            }
            uint32_t soff = (uint32_t)arow * 128u + (uint32_t)(((kg0 + c) ^ (arow & 7)) << 4);
            *(uint4*)(smem + A_BUF(0) + soff) = make_uint4(hv[0], hv[1], hv[2], hv[3]);
        }
    }
    if (mycode != -2) {
        const float* p = wrow + KCH + acol;
        raw[0] = *(const float4*)(p + 0);
        raw[1] = *(const float4*)(p + 4);
        raw[2] = *(const float4*)(p + 8);
        raw[3] = *(const float4*)(p + 12);
    }

    uint32_t a_mbase[2], a_msw[2];
    {
        int mrow0 = wm * 32 + ((lane >> 3) & 1) * 8 + (lane & 7);
        a_mbase[0] = (uint32_t)mrow0 * 128u;
        a_mbase[1] = (uint32_t)(mrow0 + 16) * 128u;
        a_msw[0] = (uint32_t)(mrow0 & 7);
        a_msw[1] = (uint32_t)((mrow0 + 16) & 7);
    }
    const uint32_t a_hi_lane = (uint32_t)(lane >> 4);
    const int klocal = ((lane >> 3) & 1) * 8 + (lane & 7);
    const uint32_t b_kbase = (uint32_t)klocal * 512u;
    const uint32_t b_ksw   = (uint32_t)(klocal & 7);
    const uint32_t b_nidx0 = (uint32_t)(wq * 8 + (lane >> 4));

    float acc[2][8][4];
    #pragma unroll
    for (int i = 0; i < 2; i++)
        #pragma unroll
        for (int j = 0; j < 8; j++)
            #pragma unroll
            for (int q = 0; q < 4; q++) acc[i][j][q] = 0.f;

    // one k16 step: batch frag loads, fire 16 MMAs
    auto mma_step = [&](int s, uint32_t a_buf, uint32_t bbuf) {
        uint32_t ah[2][4], bh[4][4];
        #pragma unroll
        for (int mt = 0; mt < 2; mt++) {
            uint32_t ci  = (uint32_t)(2 * s) + a_hi_lane;
            uint32_t off = a_mbase[mt] + ((ci ^ a_msw[mt]) << 4);
            LDSM_X4(ah[mt], a_buf + off);
        }
        #pragma unroll
        for (int np = 0; np < 4; np++) {
            uint32_t offB = (uint32_t)(s * 8192) + b_kbase +
                            (((b_nidx0 + (uint32_t)(2 * np)) ^ b_ksw) << 4);
            LDSM_X4_T(bh[np], bbuf + offB);
        }
        #pragma unroll
        for (int np = 0; np < 4; np++) {
            #pragma unroll
            for (int mt = 0; mt < 2; mt++) {
                #pragma unroll
                for (int nn = 0; nn < 2; nn++) {
                    mma16816(acc[mt][np * 2 + nn], ah[mt], bh[np] + 2 * nn);
                }
            }
        }
    };

    #pragma unroll 1
    for (int ch = 0; ch < NCH; ch++) {
        CP_WAIT0();          // B(ch) landed
        __syncthreads();     // B(ch) + A(ch) visible; prev buffers free

        const uint32_t bbuf  = sb + ((ch & 1) ? OFF_B1 : OFF_B0);
        const uint32_t a_buf = sb + A_BUF(ch & 1);

        // ---- s=0 first: tensor pipe starts immediately after barrier ----
        mma_step(0, a_buf, bbuf);

        if (ch < NCH - 1) {
            // prefetch B(ch+1) into the other buffer
            const char* sB = (const char*)&g_W[ch + 1][nh][0];
            uint32_t dst = sb + (((ch + 1) & 1) ? OFF_B1 : OFF_B0);
            #pragma unroll
            for (int i = 0; i < 8; i++)
                CP_ASYNC16(dst + (tid + i * NTHR) * 16, sB + (tid + i * NTHR) * 16);
            CP_COMMIT();

            // convert raw(ch+1) -> A buf[(ch+1)&1] (hidden under s0 MMA drain)
            float v[16];
            #pragma unroll
            for (int i = 0; i < 4; i++) {
                v[4*i+0] = raw[i].x; v[4*i+1] = raw[i].y;
                v[4*i+2] = raw[i].z; v[4*i+3] = raw[i].w;
            }
            if (mycode == -2) {
                #pragma unroll
                for (int j = 0; j < 16; j++) v[j] = 0.f;
            } else if (mycode >= 1) {
                const float* rp = rep_s + (mycode - 1) * NIS + (ch + 1) * KCH + acol;
                #pragma unroll
                for (int j = 0; j < 16; j++) v[j] += rp[j];
            }
            uint32_t abuf_w = (uint32_t)((ch + 1) & 1);
            #pragma unroll
            for (int c = 0; c < 2; c++) {
                uint32_t hv[4];
                #pragma unroll
                for (int p = 0; p < 4; p++) {
                    __half2 hh = __floats2half2_rn(v[c*8 + 2*p], v[c*8 + 2*p + 1]);
                    hv[p] = *(uint32_t*)&hh;
                }
                uint32_t soff = (uint32_t)arow * 128u + (uint32_t)(((kg0 + c) ^ (arow & 7)) << 4);
                *(uint4*)(smem + A_BUF(abuf_w) + soff) = make_uint4(hv[0], hv[1], hv[2], hv[3]);
            }
            // prefetch raw(ch+2)
            if (ch + 2 < NCH && mycode != -2) {
                const float* p = wrow + (ch + 2) * KCH + acol;
                raw[0] = *(const float4*)(p + 0);
                raw[1] = *(const float4*)(p + 4);
                raw[2] = *(const float4*)(p + 8);
                raw[3] = *(const float4*)(p + 12);
            }
        }

        // ---- remaining k16 steps ----
        mma_step(1, a_buf, bbuf);
        mma_step(2, a_buf, bbuf);
        mma_step(3, a_buf, bbuf);
    }

    // ---- epilogue ----
    __syncthreads();
    float* red = (float*)(smem + OFF_RED);
    const int rslot = wq * 4 + (lane & 3);
    #pragma unroll
    for (int mt = 0; mt < 2; mt++) {
        #pragma unroll
        for (int rh = 0; rh < 2; rh++) {
            float s0 = 0.f, s1 = 0.f, s2 = 0.f;
            #pragma unroll
            for (int nt = 0; nt < 8; nt++) {
                int col_g = nh * NTILE + wq * 64 + nt * 8 + (lane & 3) * 2;
                #pragma unroll
                for (int cc = 0; cc < 2; cc++) {
                    float h = fast_tanh(acc[mt][nt][rh * 2 + cc] + b1[col_g + cc]);
                    s0 = fmaf(h, W2[(col_g + cc) * 3 + 0], s0);
                    s1 = fmaf(h, W2[(col_g + cc) * 3 + 1], s1);
                    s2 = fmaf(h, W2[(col_g + cc) * 3 + 2], s2);
                }
            }
            int row = wm * 32 + mt * 16 + rh * 8 + (lane >> 2);
            float* rp = red + (size_t)row * 48 + rslot * 3;
            rp[0] = s0; rp[1] = s1; rp[2] = s2;
        }
    }
    __syncthreads();
    if (tid < MTILE) {
        int oslot = tile * MTILE + tid;
        if (oslot < nv) {
            float s0 = 0.f, s1 = 0.f, s2 = 0.f;
            const float* rp = red + (size_t)tid * 48;
            #pragma unroll
            for (int s = 0; s < 16; s++) {
                s0 += rp[s * 3 + 0];
                s1 += rp[s * 3 + 1];
                s2 += rp[s * 3 + 2];
            }
            int grow = g_rowidx[oslot];
            g_part[nh][grow][0] = s0;
            g_part[nh][grow][1] = s1;
            g_part[nh][grow][2] = s2;
        }
    }
}

// ---------------- combine: valid rows only, 1 row per thread ----------------
__global__ void combine_kernel(const float* __restrict__ b2,
                               float* __restrict__ out) {
    int m = blockIdx.x * blockDim.x + threadIdx.x;
    if (m >= NM) return;
    if (g_code[m] != -2) {
        out[(size_t)m * 3 + 0] = g_part[0][m][0] + g_part[1][m][0] + b2[0];
        out[(size_t)m * 3 + 1] = g_part[0][m][1] + g_part[1][m][1] + b2[1];
        out[(size_t)m * 3 + 2] = g_part[0][m][2] + g_part[1][m][2] + b2[2];
    }
}

// ---------------- launch ----------------
extern "C" void kernel_launch(void* const* d_in, const int* in_sizes, int n_in,
                              void* d_out, int out_size) {
    const float* wenc   = (const float*)d_in[0];
    const float* repeat = (const float*)d_in[1];
    const float* W1     = (const float*)d_in[2];
    const float* b1     = (const float*)d_in[3];
    const float* W2     = (const float*)d_in[4];
    const float* b2     = (const float*)d_in[5];
    const int*   wn     = (const int*)d_in[6];
    const int*   wc     = (const int*)d_in[7];
    float* out = (float*)d_out;
    (void)in_sizes; (void)n_in; (void)out_size;

    prep_all<<<PREPW + NBLK + 1, 256>>>(W1, wn, wc, b1, W2, b2);
    compact_scatter<<<NBLK, CBLK>>>(out);

    cudaFuncSetAttribute(wop_main_kernel,
                         cudaFuncAttributeMaxDynamicSharedMemorySize, SMEM_BYTES);
    wop_main_kernel<<<(NM / MTILE) * 2, NTHR, SMEM_BYTES>>>(
        wenc, repeat, b1, W2);

    combine_kernel<<<(NM + 255) / 256, 256>>>(b2, out);
}